// round 1
// baseline (speedup 1.0000x reference)
#include <cuda_runtime.h>
#include <cstddef>

#define TT 16
#define HEADS 8
#define DH 40
#define CC 320
#define SPATIAL 1024
#define NSLAB 64
#define SLAB (CC * SPATIAL)

// Scratch: Q, K, V, O buffers, each [64][320][1024] fp32
__device__ float g_scratch[4ull * NSLAB * SLAB];

// ---------------- f32x2 helpers (packed fp32 FMA: 2x FFMA throughput) ----------
__device__ __forceinline__ unsigned long long bcast2(float v) {
    unsigned long long r;
    unsigned int u = __float_as_uint(v);
    asm("mov.b64 %0, {%1, %1};" : "=l"(r) : "r"(u));
    return r;
}
__device__ __forceinline__ void ffma2(unsigned long long& d,
                                      unsigned long long a,
                                      unsigned long long b) {
    asm("fma.rn.f32x2 %0, %1, %2, %0;" : "+l"(d) : "l"(a), "l"(b));
}
__device__ __forceinline__ float2 unpack2(unsigned long long p) {
    unsigned int lo, hi;
    asm("mov.b64 {%0, %1}, %2;" : "=r"(lo), "=r"(hi) : "l"(p));
    return make_float2(__uint_as_float(lo), __uint_as_float(hi));
}

// ---------------- Batched slab GEMM: C[slab] = W @ X[slab] (+ bias + residual) --
// W: [320,320] row-major.  X,C: [64][320][1024].  Tile: BM=64, BN=128, BK=32.
// 256 threads, each computes 4(m) x 8(n) via f32x2 pairs.
__global__ __launch_bounds__(256) void gemm_slab(
    const float* __restrict__ W,
    const float* __restrict__ Xall,
    float* __restrict__ Call,
    const float* __restrict__ bias,   // nullptr or [320]
    const float* __restrict__ Rall)   // nullptr or residual, same layout as Call
{
    __shared__ float As[32 * 65];     // [k][m], padded stride 65 -> conflict-free
    __shared__ float Bs[32 * 128];    // [k][n]

    const int slab = blockIdx.z;
    const float* X = Xall + (size_t)slab * SLAB;
    float* C = Call + (size_t)slab * SLAB;

    const int tid = threadIdx.x;
    const int m0 = blockIdx.y * 64;
    const int n0 = blockIdx.x * 128;
    const int ty = tid >> 4;          // 0..15 -> m = ty*4
    const int tx = tid & 15;          // 0..15 -> n = tx*8

    const int arow = tid >> 3;        // 0..31
    const int acol = (tid & 7) << 2;  // 0..28
    const int brow = tid >> 5;        // 0..7
    const int bcol = (tid & 31) << 2; // 0..124

    unsigned long long acc[4][4];
#pragma unroll
    for (int i = 0; i < 4; i++)
#pragma unroll
        for (int j = 0; j < 4; j++) acc[i][j] = 0ull;

    for (int kt = 0; kt < CC; kt += 32) {
        float4 a0 = *(const float4*)(W + (size_t)(m0 + arow) * CC + kt + acol);
        float4 a1 = *(const float4*)(W + (size_t)(m0 + arow + 32) * CC + kt + acol);
        float4 b0 = *(const float4*)(X + (size_t)(kt + brow)      * SPATIAL + n0 + bcol);
        float4 b1 = *(const float4*)(X + (size_t)(kt + brow + 8)  * SPATIAL + n0 + bcol);
        float4 b2 = *(const float4*)(X + (size_t)(kt + brow + 16) * SPATIAL + n0 + bcol);
        float4 b3 = *(const float4*)(X + (size_t)(kt + brow + 24) * SPATIAL + n0 + bcol);

        __syncthreads();  // previous iteration's compute done

        As[(acol + 0) * 65 + arow] = a0.x;
        As[(acol + 1) * 65 + arow] = a0.y;
        As[(acol + 2) * 65 + arow] = a0.z;
        As[(acol + 3) * 65 + arow] = a0.w;
        As[(acol + 0) * 65 + arow + 32] = a1.x;
        As[(acol + 1) * 65 + arow + 32] = a1.y;
        As[(acol + 2) * 65 + arow + 32] = a1.z;
        As[(acol + 3) * 65 + arow + 32] = a1.w;
        *(float4*)(Bs + (brow)      * 128 + bcol) = b0;
        *(float4*)(Bs + (brow + 8)  * 128 + bcol) = b1;
        *(float4*)(Bs + (brow + 16) * 128 + bcol) = b2;
        *(float4*)(Bs + (brow + 24) * 128 + bcol) = b3;

        __syncthreads();

#pragma unroll
        for (int k = 0; k < 32; k++) {
            unsigned long long a2[4];
#pragma unroll
            for (int i = 0; i < 4; i++)
                a2[i] = bcast2(As[k * 65 + ty * 4 + i]);
            const unsigned long long* bp =
                (const unsigned long long*)(Bs + k * 128 + tx * 8);
            unsigned long long bb[4];
#pragma unroll
            for (int j = 0; j < 4; j++) bb[j] = bp[j];
#pragma unroll
            for (int i = 0; i < 4; i++)
#pragma unroll
                for (int j = 0; j < 4; j++) ffma2(acc[i][j], a2[i], bb[j]);
        }
    }

#pragma unroll
    for (int i = 0; i < 4; i++) {
        const int row = m0 + ty * 4 + i;
        float v[8];
#pragma unroll
        for (int j = 0; j < 4; j++) {
            float2 p = unpack2(acc[i][j]);
            v[2 * j] = p.x;
            v[2 * j + 1] = p.y;
        }
        const size_t off = (size_t)row * SPATIAL + n0 + tx * 8;
        if (bias != nullptr) {
            const float bb = bias[row];
            float4 r0 = *(const float4*)(Rall + (size_t)slab * SLAB + off);
            float4 r1 = *(const float4*)(Rall + (size_t)slab * SLAB + off + 4);
            v[0] += bb + r0.x; v[1] += bb + r0.y; v[2] += bb + r0.z; v[3] += bb + r0.w;
            v[4] += bb + r1.x; v[5] += bb + r1.y; v[6] += bb + r1.z; v[7] += bb + r1.w;
        }
        *(float4*)(C + off)     = make_float4(v[0], v[1], v[2], v[3]);
        *(float4*)(C + off + 4) = make_float4(v[4], v[5], v[6], v[7]);
    }
}

// ---------------- Attention kernel --------------------------------------------
// Block = (b, h, 32 spatial sequences). K,V tiles staged in smem [f][d][32],
// rel tables in smem. Warp tg handles query frames t = tg and t = 15 - tg
// (constant total work per warp). Causal softmax, fully register-resident.
__global__ __launch_bounds__(256) void attn_kernel(
    const float* __restrict__ Qg, const float* __restrict__ Kg,
    const float* __restrict__ Vg, float* __restrict__ Og,
    const float* __restrict__ relk, const float* __restrict__ relv)
{
    extern __shared__ float sm[];
    float* Ks = sm;             // 16*40*32 = 20480
    float* Vs = sm + 20480;     // 20480
    float* Rk = sm + 40960;     // 33*40 = 1320
    float* Rv = sm + 42280;     // 1320  (total 43600 floats = 174400 B)

    const int b = blockIdx.z;
    const int h = blockIdx.y;
    const int s0 = blockIdx.x * 32;
    const int tid = threadIdx.x;

    for (int i = tid; i < TT * DH * 32; i += 256) {
        const int row = i >> 5, sl2 = i & 31;
        const int f = row / DH, dd = row - f * DH;
        const size_t g =
            ((size_t)((b * TT + f) * CC + h * DH + dd)) * SPATIAL + s0 + sl2;
        Ks[i] = Kg[g];
        Vs[i] = Vg[g];
    }
    for (int i = tid; i < 33 * DH; i += 256) {
        Rk[i] = relk[i];
        Rv[i] = relv[i];
    }
    __syncthreads();

    const int sl = tid & 31;
    const int tg = tid >> 5;
    const float scale = 0.15811388300841898f;  // 40^-0.5

    for (int rep = 0; rep < 2; rep++) {
        const int t = rep ? (15 - tg) : tg;   // warp-uniform
        const size_t base =
            ((size_t)((b * TT + t) * CC + h * DH)) * SPATIAL + s0 + sl;

        float q[DH];
#pragma unroll
        for (int dd = 0; dd < DH; dd++) q[dd] = Qg[base + (size_t)dd * SPATIAL];

        float sim[TT];
        float mx = -1e30f;
#pragma unroll
        for (int sp = 0; sp < TT; sp++) {
            if (sp > t) break;                // warp-uniform branch
            const float* kp = Ks + (sp * DH) * 32 + sl;
            const float* rp = Rk + (sp - t + TT) * DH;
            float acc = 0.f;
#pragma unroll
            for (int dd = 0; dd < DH; dd++) acc += q[dd] * (kp[dd * 32] + rp[dd]);
            acc *= scale;
            sim[sp] = acc;
            mx = fmaxf(mx, acc);
        }
        float den = 0.f;
#pragma unroll
        for (int sp = 0; sp < TT; sp++) {
            if (sp > t) break;
            const float e = __expf(sim[sp] - mx);
            sim[sp] = e;
            den += e;
        }
        const float inv = 1.f / den;

        float o[DH];
#pragma unroll
        for (int dd = 0; dd < DH; dd++) o[dd] = 0.f;
#pragma unroll
        for (int sp = 0; sp < TT; sp++) {
            if (sp > t) break;
            const float a = sim[sp];
            const float* vp = Vs + (sp * DH) * 32 + sl;
            const float* rp = Rv + (sp - t + TT) * DH;
#pragma unroll
            for (int dd = 0; dd < DH; dd++) o[dd] += a * (vp[dd * 32] + rp[dd]);
        }
#pragma unroll
        for (int dd = 0; dd < DH; dd++)
            Og[base + (size_t)dd * SPATIAL] = o[dd] * inv;
    }
}

// ---------------- launch -------------------------------------------------------
extern "C" void kernel_launch(void* const* d_in, const int* in_sizes, int n_in,
                              void* d_out, int out_size) {
    const float* x  = (const float*)d_in[0];
    const float* Wq = (const float*)d_in[1];
    const float* Wk = (const float*)d_in[2];
    const float* Wv = (const float*)d_in[3];
    const float* Wo = (const float*)d_in[4];
    const float* bo = (const float*)d_in[5];
    const float* rk = (const float*)d_in[6];
    const float* rv = (const float*)d_in[7];
    float* out = (float*)d_out;

    float* sc = nullptr;
    cudaGetSymbolAddress((void**)&sc, g_scratch);
    float* Q = sc;
    float* K = sc + 1ull * NSLAB * SLAB;
    float* V = sc + 2ull * NSLAB * SLAB;
    float* O = sc + 3ull * NSLAB * SLAB;

    dim3 gg(SPATIAL / 128, CC / 64, NSLAB);  // (8, 5, 64)
    gemm_slab<<<gg, 256>>>(Wq, x, Q, nullptr, nullptr);
    gemm_slab<<<gg, 256>>>(Wk, x, K, nullptr, nullptr);
    gemm_slab<<<gg, 256>>>(Wv, x, V, nullptr, nullptr);

    const int smb = 43600 * 4;  // 174400 bytes dynamic smem
    cudaFuncSetAttribute((const void*)attn_kernel,
                         cudaFuncAttributeMaxDynamicSharedMemorySize, smb);
    attn_kernel<<<dim3(SPATIAL / 32, HEADS, 4), 256, smb>>>(Q, K, V, O, rk, rv);

    gemm_slab<<<gg, 256>>>(Wo, O, out, bo, x);
}

// round 2
// speedup vs baseline: 2.9714x; 2.9714x over previous
#include <cuda_runtime.h>
#include <cstdint>
#include <cstddef>

#define TT 16
#define HEADS 8
#define DH 40
#define CC 320
#define SPATIAL 1024
#define NSLAB 64
#define SLAB (CC * SPATIAL)

// Scratch: Q, K, V, O buffers, each [64][320][1024] fp32
__device__ float g_scratch[4ull * NSLAB * SLAB];

// ---------------- helpers ------------------------------------------------------
__device__ __forceinline__ uint32_t smem_u32(const void* p) {
    uint32_t a;
    asm("{ .reg .u64 t; cvta.to.shared.u64 t, %1; cvt.u32.u64 %0, t; }"
        : "=r"(a) : "l"(p));
    return a;
}
__device__ __forceinline__ float to_tf32(float x) {
    float r;
    asm("cvt.rna.tf32.f32 %0, %1;" : "=f"(r) : "f"(x));
    return r;
}
__device__ __forceinline__ void ldsm4(uint32_t& r0, uint32_t& r1, uint32_t& r2,
                                      uint32_t& r3, uint32_t a) {
    asm volatile("ldmatrix.sync.aligned.m8n8.x4.shared.b16 {%0,%1,%2,%3}, [%4];"
                 : "=r"(r0), "=r"(r1), "=r"(r2), "=r"(r3) : "r"(a));
}
__device__ __forceinline__ void mma8(float* c, uint32_t a0, uint32_t a1,
                                     uint32_t a2, uint32_t a3,
                                     uint32_t b0, uint32_t b1) {
    asm volatile(
        "mma.sync.aligned.m16n8k8.row.col.f32.tf32.tf32.f32 "
        "{%0,%1,%2,%3},{%4,%5,%6,%7},{%8,%9},{%0,%1,%2,%3};"
        : "+f"(c[0]), "+f"(c[1]), "+f"(c[2]), "+f"(c[3])
        : "r"(a0), "r"(a1), "r"(a2), "r"(a3), "r"(b0), "r"(b1));
}

// ---------------- tf32 tensor-core GEMM core -----------------------------------
// C[BM=64, BN=128] tile of  C = W[320,320] @ X[320,1024]  (per slab)
// 256 threads = 8 warps (2m x 4n), warp tile 32x32, BK=32, fp32 accumulate.
template <bool EPI>
__device__ __forceinline__ void gemm_core(
    const float* __restrict__ W, const float* __restrict__ X,
    float* __restrict__ C, const float* __restrict__ bias,
    const float* __restrict__ R, int m0, int n0)
{
    __shared__ float As[64 * 36];   // [m][k], stride 36 (16B-aligned rows)
    __shared__ float Bs[32 * 132];  // [k][n], stride 132

    const int tid = threadIdx.x;
    const int lane = tid & 31, wid = tid >> 5;
    const int wm = (wid & 1) * 32, wn = (wid >> 1) * 32;

    float c[2][4][4];
#pragma unroll
    for (int i = 0; i < 2; i++)
#pragma unroll
        for (int j = 0; j < 4; j++)
#pragma unroll
            for (int k = 0; k < 4; k++) c[i][j][k] = 0.f;

    const int ar = tid >> 3;          // 0..31
    const int ac = (tid & 7) << 2;    // 0..28

    const uint32_t as_base = smem_u32(As);
    // ldmatrix per-thread row (within warp m-tile), k-word select
    const int afrow = wm + (lane & 7) + ((lane >> 3) & 1) * 8;  // + mt*16
    const int akw = (lane >> 4) << 2;                           // 0 or 4

    for (int kt = 0; kt < CC; kt += 32) {
        float4 a0 = *(const float4*)(W + (size_t)(m0 + ar) * CC + kt + ac);
        float4 a1 = *(const float4*)(W + (size_t)(m0 + ar + 32) * CC + kt + ac);
        float4 bv[4];
        int kr[4], nc[4];
#pragma unroll
        for (int i = 0; i < 4; i++) {
            const int f = i * 256 + tid;
            kr[i] = f >> 5;
            nc[i] = (f & 31) << 2;
            bv[i] = *(const float4*)(X + (size_t)(kt + kr[i]) * SPATIAL + n0 + nc[i]);
        }

        __syncthreads();

        *(float4*)(As + ar * 36 + ac) =
            make_float4(to_tf32(a0.x), to_tf32(a0.y), to_tf32(a0.z), to_tf32(a0.w));
        *(float4*)(As + (ar + 32) * 36 + ac) =
            make_float4(to_tf32(a1.x), to_tf32(a1.y), to_tf32(a1.z), to_tf32(a1.w));
#pragma unroll
        for (int i = 0; i < 4; i++) {
            *(float4*)(Bs + kr[i] * 132 + nc[i]) =
                make_float4(to_tf32(bv[i].x), to_tf32(bv[i].y),
                            to_tf32(bv[i].z), to_tf32(bv[i].w));
        }

        __syncthreads();

#pragma unroll
        for (int s = 0; s < 4; s++) {
            uint32_t af[2][4];
#pragma unroll
            for (int mt = 0; mt < 2; mt++) {
                const uint32_t addr =
                    as_base + (uint32_t)(((afrow + mt * 16) * 36 + s * 8 + akw) * 4);
                ldsm4(af[mt][0], af[mt][1], af[mt][2], af[mt][3], addr);
            }
#pragma unroll
            for (int nt = 0; nt < 4; nt++) {
                const int bi = (s * 8 + (lane & 3)) * 132 + wn + nt * 8 + (lane >> 2);
                const uint32_t b0 = __float_as_uint(Bs[bi]);
                const uint32_t b1 = __float_as_uint(Bs[bi + 4 * 132]);
                mma8(c[0][nt], af[0][0], af[0][1], af[0][2], af[0][3], b0, b1);
                mma8(c[1][nt], af[1][0], af[1][1], af[1][2], af[1][3], b0, b1);
            }
        }
    }

#pragma unroll
    for (int mt = 0; mt < 2; mt++) {
#pragma unroll
        for (int nt = 0; nt < 4; nt++) {
            const int r0 = m0 + wm + mt * 16 + (lane >> 2);
            const int col = n0 + wn + nt * 8 + (lane & 3) * 2;
            const size_t o0 = (size_t)r0 * SPATIAL + col;
            const size_t o1 = o0 + 8ull * SPATIAL;
            float v0 = c[mt][nt][0], v1 = c[mt][nt][1];
            float v2 = c[mt][nt][2], v3 = c[mt][nt][3];
            if (EPI) {
                const float b0v = bias[r0], b1v = bias[r0 + 8];
                const float2 x0 = *(const float2*)(R + o0);
                const float2 x1 = *(const float2*)(R + o1);
                v0 += b0v + x0.x; v1 += b0v + x0.y;
                v2 += b1v + x1.x; v3 += b1v + x1.y;
            }
            *(float2*)(C + o0) = make_float2(v0, v1);
            *(float2*)(C + o1) = make_float2(v2, v3);
        }
    }
}

// Fused QKV projection: blockIdx.y in [0,15): wsel = y/5 picks W + output buffer.
__global__ __launch_bounds__(256) void qkv_gemm(
    const float* __restrict__ Wq, const float* __restrict__ Wk,
    const float* __restrict__ Wv, const float* __restrict__ X,
    float* __restrict__ out)
{
    const int slab = blockIdx.z;
    const int wsel = blockIdx.y / 5, mblk = blockIdx.y % 5;
    const float* W = (wsel == 0) ? Wq : ((wsel == 1) ? Wk : Wv);
    gemm_core<false>(W, X + (size_t)slab * SLAB,
                     out + (size_t)wsel * NSLAB * SLAB + (size_t)slab * SLAB,
                     nullptr, nullptr, mblk * 64, blockIdx.x * 128);
}

// Output projection with bias + residual fused.
__global__ __launch_bounds__(256) void o_gemm(
    const float* __restrict__ Wo, const float* __restrict__ O,
    const float* __restrict__ bo, const float* __restrict__ X,
    float* __restrict__ out)
{
    const int slab = blockIdx.z;
    gemm_core<true>(Wo, O + (size_t)slab * SLAB, out + (size_t)slab * SLAB,
                    bo, X + (size_t)slab * SLAB, blockIdx.y * 64,
                    blockIdx.x * 128);
}

// ---------------- Attention kernel --------------------------------------------
// Block = (b, h, 32 spatial sequences), 512 threads = 16 warps; warp tg owns
// query frame t = tg. K,V staged in smem [f][d][32] + rel tables.
__global__ __launch_bounds__(512) void attn_kernel(
    const float* __restrict__ Qg, const float* __restrict__ Kg,
    const float* __restrict__ Vg, float* __restrict__ Og,
    const float* __restrict__ relk, const float* __restrict__ relv)
{
    extern __shared__ float sm[];
    float* Ks = sm;             // 16*40*32 = 20480
    float* Vs = sm + 20480;     // 20480
    float* Rk = sm + 40960;     // 33*40 = 1320
    float* Rv = sm + 42280;     // 1320  (total 43600 floats = 174400 B)

    const int b = blockIdx.z;
    const int h = blockIdx.y;
    const int s0 = blockIdx.x * 32;
    const int tid = threadIdx.x;

    for (int i = tid; i < TT * DH * 32; i += 512) {
        const int row = i >> 5, sl2 = i & 31;
        const int f = row / DH, dd = row - f * DH;
        const size_t g =
            ((size_t)((b * TT + f) * CC + h * DH + dd)) * SPATIAL + s0 + sl2;
        Ks[i] = Kg[g];
        Vs[i] = Vg[g];
    }
    for (int i = tid; i < 33 * DH; i += 512) {
        Rk[i] = relk[i];
        Rv[i] = relv[i];
    }
    __syncthreads();

    const int sl = tid & 31;
    const int t = tid >> 5;                 // 0..15, warp-uniform
    const float scale = 0.15811388300841898f;  // 40^-0.5

    const size_t base =
        ((size_t)((b * TT + t) * CC + h * DH)) * SPATIAL + s0 + sl;

    float q[DH];
#pragma unroll
    for (int dd = 0; dd < DH; dd++) q[dd] = Qg[base + (size_t)dd * SPATIAL];

    float sim[TT];
    float mx = -1e30f;
#pragma unroll
    for (int sp = 0; sp < TT; sp++) {
        if (sp > t) break;                  // warp-uniform branch
        const float* kp = Ks + (sp * DH) * 32 + sl;
        const float* rp = Rk + (sp - t + TT) * DH;
        float acc = 0.f;
#pragma unroll
        for (int dd = 0; dd < DH; dd++) acc += q[dd] * (kp[dd * 32] + rp[dd]);
        acc *= scale;
        sim[sp] = acc;
        mx = fmaxf(mx, acc);
    }
    float den = 0.f;
#pragma unroll
    for (int sp = 0; sp < TT; sp++) {
        if (sp > t) break;
        const float e = __expf(sim[sp] - mx);
        sim[sp] = e;
        den += e;
    }
    const float inv = 1.f / den;

    float o[DH];
#pragma unroll
    for (int dd = 0; dd < DH; dd++) o[dd] = 0.f;
#pragma unroll
    for (int sp = 0; sp < TT; sp++) {
        if (sp > t) break;
        const float a = sim[sp];
        const float* vp = Vs + (sp * DH) * 32 + sl;
        const float* rp = Rv + (sp - t + TT) * DH;
#pragma unroll
        for (int dd = 0; dd < DH; dd++) o[dd] += a * (vp[dd * 32] + rp[dd]);
    }
#pragma unroll
    for (int dd = 0; dd < DH; dd++)
        Og[base + (size_t)dd * SPATIAL] = o[dd] * inv;
}

// ---------------- launch -------------------------------------------------------
extern "C" void kernel_launch(void* const* d_in, const int* in_sizes, int n_in,
                              void* d_out, int out_size) {
    const float* x  = (const float*)d_in[0];
    const float* Wq = (const float*)d_in[1];
    const float* Wk = (const float*)d_in[2];
    const float* Wv = (const float*)d_in[3];
    const float* Wo = (const float*)d_in[4];
    const float* bo = (const float*)d_in[5];
    const float* rk = (const float*)d_in[6];
    const float* rv = (const float*)d_in[7];
    float* out = (float*)d_out;

    float* sc = nullptr;
    cudaGetSymbolAddress((void**)&sc, g_scratch);
    float* Q = sc;                           // wsel 0
    float* V = sc + 2ull * NSLAB * SLAB;     // wsel 2
    float* K = sc + 1ull * NSLAB * SLAB;     // wsel 1
    float* O = sc + 3ull * NSLAB * SLAB;

    qkv_gemm<<<dim3(SPATIAL / 128, 15, NSLAB), 256>>>(Wq, Wk, Wv, x, sc);

    const int smb = 43600 * 4;  // 174400 bytes dynamic smem
    cudaFuncSetAttribute((const void*)attn_kernel,
                         cudaFuncAttributeMaxDynamicSharedMemorySize, smb);
    attn_kernel<<<dim3(SPATIAL / 32, HEADS, 4), 512, smb>>>(Q, K, V, O, rk, rv);

    o_gemm<<<dim3(SPATIAL / 128, CC / 64, NSLAB), 256>>>(Wo, O, bo, x, out);
}